// round 4
// baseline (speedup 1.0000x reference)
#include <cuda_runtime.h>

// SuperLinear: out[b,n] = sum_m x[b,n,m] * w1[m,0,n] + b1[0,n,0]
// x[B=256, N=4096, M=64], w1[64,1,4096], b1[1,4096,1], out[B,N].
//
// R3b: w + bias hoisted from shared into REGISTERS once per block (each lane
// owns 4 output rows x its float4 m-chunk = 16 w regs). Hot loop over b is:
// 4x LDG.128 front-batched (MLP>=4) -> 4x (4 FMA + 4 butterfly SHFL) -> STG.
// No LDS in the loop. BTILE=8 -> 2048 blocks (~3 waves) to smooth tail
// imbalance from per-SM spread.

#define N_DIM   4096
#define M_DIM   64
#define NTILE   64          // n-values per block
#define BTILE   8           // b-values per block
#define WROW    68          // padded shared row stride (floats)

__global__ __launch_bounds__(256)
void superlinear_kernel(const float* __restrict__ x,
                        const float* __restrict__ w,
                        const float* __restrict__ bias,
                        float* __restrict__ out) {
    __shared__ float w_s[NTILE][WROW];   // w_s[n_loc][m]
    __shared__ float b_s[NTILE];

    const int tid = threadIdx.x;
    const int bx  = blockIdx.x;
    const int n0  = (bx & (N_DIM / NTILE - 1)) * NTILE;   // 64 n-tiles
    const int b0  = (bx >> 6) * BTILE;                    // N_DIM/NTILE == 64

    // ---- Stage w tile (transposed) + bias into shared, coalesced over n ----
    {
        const int n_loc = tid & (NTILE - 1);
        const int m_hi  = tid >> 6;            // 0..3
        #pragma unroll
        for (int mb = 0; mb < M_DIM; mb += 4)
            w_s[n_loc][mb + m_hi] = w[(size_t)(mb + m_hi) * N_DIM + n0 + n_loc];
        if (tid < NTILE)
            b_s[tid] = bias[n0 + tid];
    }
    __syncthreads();

    const int warp = tid >> 5;           // 0..7
    const int lane = tid & 31;
    const int half = lane >> 4;          // 0 or 1
    const int sub  = lane & 15;          // lane within 16-lane group

    // ---- Hoist this lane's weights + bias into registers (once) ----
    // Output rows owned by this 16-lane group: n_loc = p*16 + warp*2 + half.
    float4 wr[4];
    float  br[4];
    const int nlb = warp * 2 + half;     // base n_loc; row p is nlb + 16p
    #pragma unroll
    for (int p = 0; p < 4; p++) {
        wr[p] = *reinterpret_cast<const float4*>(&w_s[nlb + p * 16][sub * 4]);
        br[p] = b_s[nlb + p * 16];
    }

    const float4* __restrict__ x4 = reinterpret_cast<const float4*>(x);

    // ---- Hot loop: stream x ----
    #pragma unroll 1
    for (int bb = 0; bb < BTILE; bb++) {
        const size_t rowbase = (size_t)(b0 + bb) * N_DIM + n0 + nlb;

        // Front-batch all four 128-bit loads (independent -> MLP >= 4).
        float4 xv[4];
        #pragma unroll
        for (int p = 0; p < 4; p++)
            xv[p] = __ldg(x4 + (rowbase + p * 16) * (M_DIM / 4) + sub);

        #pragma unroll
        for (int p = 0; p < 4; p++) {
            float s = xv[p].x * wr[p].x;
            s = fmaf(xv[p].y, wr[p].y, s);
            s = fmaf(xv[p].z, wr[p].z, s);
            s = fmaf(xv[p].w, wr[p].w, s);
            #pragma unroll
            for (int off = 8; off > 0; off >>= 1)
                s += __shfl_xor_sync(0xFFFFFFFFu, s, off);
            if (sub == 0)
                out[rowbase + p * 16] = s + br[p];
        }
    }
}

extern "C" void kernel_launch(void* const* d_in, const int* in_sizes, int n_in,
                              void* d_out, int out_size) {
    const float* x    = (const float*)d_in[0];   // [B, N, 64]
    const float* w1   = (const float*)d_in[1];   // [64, 1, N]
    const float* b1   = (const float*)d_in[2];   // [1, N, 1]
    float* out        = (float*)d_out;           // [B, N]

    const int B = in_sizes[0] / (N_DIM * M_DIM); // 256
    const int blocks = (B / BTILE) * (N_DIM / NTILE); // 32 * 64 = 2048

    superlinear_kernel<<<blocks, 256>>>(x, w1, b1, out);
}